// round 3
// baseline (speedup 1.0000x reference)
#include <cuda_runtime.h>
#include <cuda_bf16.h>

#define NS   5000
#define SP   10
#define NSEG 9
#define HH   512
#define HC   102
#define KK   20

// ---- device scratch (no allocations allowed) ----
__device__ float4 g_seg[NS * NSEG];   // a.x, a.y, (b-a).x, (b-a).y
__device__ float  g_inv[NS * NSEG];   // 1 / |b-a|^2
__device__ int    g_idcs[HC * HC * KK];

// ---------------- Kernel A: bezier -> segments ----------------
__global__ void bezier_kernel(const float* __restrict__ cs,
                              const float* __restrict__ ce,
                              const float* __restrict__ cc,
                              const float* __restrict__ loc) {
    int n = blockIdx.x * blockDim.x + threadIdx.x;
    if (n >= NS) return;
    float lx = loc[2*n], ly = loc[2*n+1];
    float sx = cs[2*n] + lx, sy = cs[2*n+1] + ly;
    float ex = ce[2*n] + lx, ey = ce[2*n+1] + ly;
    float cx = cc[2*n] + lx, cy = cc[2*n+1] + ly;
    // (s-c), (e-c) AFTER adding location (matches reference op order)
    float scx = sx - cx, scy = sy - cy;
    float ecx = ex - cx, ecy = ey - cy;
    float px[SP], py[SP];
    const float step = 1.0f / 9.0f;
    #pragma unroll
    for (int j = 0; j < SP; j++) {
        float t = (float)j * step;
        float omt = 1.0f - t;
        float omt2 = omt * omt, t2 = t * t;
        px[j] = cx + omt2 * scx + t2 * ecx;
        py[j] = cy + omt2 * scy + t2 * ecy;
    }
    #pragma unroll
    for (int q = 0; q < NSEG; q++) {
        float ax = px[q], ay = py[q];
        float bx = px[q+1] - ax, by = py[q+1] - ay;
        float len2 = bx*bx + by*by;
        g_seg[n*NSEG + q] = make_float4(ax, ay, bx, by);
        g_inv[n*NSEG + q] = 1.0f / len2;
    }
}

// ---------------- Kernel B: exact top-K per coarse cell ----------------
// One warp per cell. Keys = (dist_bits << 32) | idx  -> u64 ascending ==
// (dist asc, idx asc) == jax.lax.top_k(-D) ordering.
__global__ void topk_kernel(const float* __restrict__ loc) {
    const int lane = threadIdx.x & 31;
    const int wi   = threadIdx.x >> 5;
    const int cell = blockIdx.x * (blockDim.x >> 5) + wi;
    __shared__ unsigned long long lists[4][32][KK];   // blockDim = 128
    if (cell >= HC * HC) return;

    int cy = cell / HC, cx = cell - cy * HC;
    const float cstep = 512.0f / 101.0f;
    float pxc = (float)cy * cstep;
    float pyc = (float)cx * cstep;

    unsigned long long* my = lists[wi][lane];
    #pragma unroll
    for (int j = 0; j < KK; j++) my[j] = 0xFFFFFFFFFFFFFFFFULL;
    unsigned long long kthkey = 0xFFFFFFFFFFFFFFFFULL;

    for (int n = lane; n < NS; n += 32) {
        float dx = pxc - __ldg(&loc[2*n]);
        float dy = pyc - __ldg(&loc[2*n+1]);
        float d = dx*dx + dy*dy;
        unsigned long long key =
            ((unsigned long long)__float_as_uint(d) << 32) | (unsigned)n;
        if (key < kthkey) {
            int j = KK - 1;
            while (j > 0 && my[j-1] > key) { my[j] = my[j-1]; j--; }
            my[j] = key;
            kthkey = my[KK-1];
        }
    }

    // warp-cooperative merge of 32 sorted lists -> first KK
    int h = 0;
    for (int r = 0; r < KK; r++) {
        unsigned long long mykey = my[h];
        unsigned long long mn = mykey;
        #pragma unroll
        for (int off = 16; off; off >>= 1) {
            unsigned long long o = __shfl_xor_sync(0xffffffffu, mn, off);
            if (o < mn) mn = o;
        }
        unsigned msk = __ballot_sync(0xffffffffu, mykey == mn);
        int leader = __ffs(msk) - 1;
        if (lane == leader) h++;
        if (lane == 0) g_idcs[cell*KK + r] = (int)(mn & 0xffffffffu);
    }
}

// ---------------- Kernel C: render ----------------
__global__ void render_kernel(const float* __restrict__ color,
                              const float* __restrict__ width,
                              float* __restrict__ out) {
    int j = blockIdx.x * blockDim.x + threadIdx.x;   // col (W / y-coord)
    int i = blockIdx.y * blockDim.y + threadIdx.y;   // row (H / x-coord)
    if (i >= HH || j >= HH) return;

    const float fstep = 512.0f / 511.0f;
    float Px = (float)i * fstep;
    float Py = (float)j * fstep;

    int cy = (i * 51) >> 8;          // floor(i * 102/512), exact
    int cx = (j * 51) >> 8;
    int base = (cy * HC + cx) * KK;

    // width bilinear coords (half-pixel, clamp == renormalized edge)
    float u = ((float)i + 0.5f) * 0.19921875f - 0.5f;
    float v = ((float)j + 0.5f) * 0.19921875f - 0.5f;
    u = fminf(fmaxf(u, 0.0f), 101.0f);
    v = fminf(fmaxf(v, 0.0f), 101.0f);
    int u0 = min((int)u, 100), v0 = min((int)v, 100);
    float fu = u - (float)u0, fv = v - (float)v0;
    int b00 = (u0 * HC + v0) * KK;
    int b01 = b00 + KK;
    int b10 = b00 + HC * KK;
    int b11 = b10 + KK;
    float wt00 = (1.0f-fu)*(1.0f-fv), wt01 = (1.0f-fu)*fv;
    float wt10 = fu*(1.0f-fv),        wt11 = fu*fv;

    const float INF = __int_as_float(0x7f800000);
    float Lmax = -INF;
    float Ssum = 0.0f, A0 = 0.0f, A1 = 0.0f, A2 = 0.0f, Wa = 0.0f;
    float Dmin = INF;

    #pragma unroll 1
    for (int k = 0; k < KK; k++) {
        int s = __ldg(&g_idcs[base + k]);
        const float4* seg = &g_seg[s * NSEG];
        const float*  inv = &g_inv[s * NSEG];
        float m = INF;
        #pragma unroll
        for (int q = 0; q < NSEG; q++) {
            float4 sg = __ldg(&seg[q]);
            float  iv = __ldg(&inv[q]);
            float pax = Px - sg.x, pay = Py - sg.y;
            float t = (sg.z * pax + sg.w * pay) * iv;
            t = fminf(fmaxf(t, 0.0f), 1.0f);
            float qx = sg.x + t * sg.z;
            float qy = sg.y + t * sg.w;
            float dx = Px - qx, dy = Py - qy;
            float d = dx*dx + dy*dy;
            m = fminf(m, d);
        }
        Dmin = fminf(Dmin, m);
        float logit = 100000.0f * (1.0f / (1e-8f + m));

        // per-slot bilinear width
        float wk = wt00 * __ldg(&width[__ldg(&g_idcs[b00 + k])])
                 + wt01 * __ldg(&width[__ldg(&g_idcs[b01 + k])])
                 + wt10 * __ldg(&width[__ldg(&g_idcs[b10 + k])])
                 + wt11 * __ldg(&width[__ldg(&g_idcs[b11 + k])]);

        float c0 = __ldg(&color[3*s]);
        float c1 = __ldg(&color[3*s+1]);
        float c2 = __ldg(&color[3*s+2]);

        // branch-free online softmax
        float nm = fmaxf(Lmax, logit);
        float so = __expf(Lmax - nm);     // 0 on first iter (exp(-inf))
        float w  = __expf(logit - nm);
        Ssum = Ssum * so + w;
        A0 = A0 * so + w * c0;
        A1 = A1 * so + w * c1;
        A2 = A2 * so + w * c2;
        Wa = Wa * so + w * wk;
        Lmax = nm;
    }

    float invS = 1.0f / Ssum;
    float bs = Wa * invS;
    float x = bs - Dmin;
    float mask = 1.0f / (1.0f + __expf(-x));
    float om = 1.0f - mask;
    int o = (i * HH + j) * 3;
    out[o+0] = A0 * invS * mask + om * 0.5f;
    out[o+1] = A1 * invS * mask + om * 0.5f;
    out[o+2] = A2 * invS * mask + om * 0.5f;
}

// ---------------- launch ----------------
extern "C" void kernel_launch(void* const* d_in, const int* in_sizes, int n_in,
                              void* d_out, int out_size) {
    const float* curve_s  = (const float*)d_in[0];
    const float* curve_e  = (const float*)d_in[1];
    const float* curve_c  = (const float*)d_in[2];
    const float* color    = (const float*)d_in[3];
    const float* location = (const float*)d_in[4];
    const float* width    = (const float*)d_in[5];
    float* out = (float*)d_out;

    bezier_kernel<<<(NS + 127) / 128, 128>>>(curve_s, curve_e, curve_c, location);

    int ncells = HC * HC;                       // 10404 = 4 * 2601
    topk_kernel<<<ncells / 4, 128>>>(location);

    dim3 blk(32, 8);
    dim3 grd((HH + 31) / 32, (HH + 7) / 8);
    render_kernel<<<grd, blk>>>(color, width, out);
}

// round 6
// speedup vs baseline: 10.6069x; 10.6069x over previous
#include <cuda_runtime.h>
#include <cuda_bf16.h>

#define NS    5000
#define SP    10
#define NSEG  9
#define HH    512
#define HC    102
#define KK    20
#define GB    16          // bin grid
#define BSZ   32.0f       // bin size in px
#define NCELL (HC*HC)

// ---- device scratch ----
__device__ float4 g_seg[NS * NSEG];   // a.x, a.y, (b-a).x, (b-a).y
__device__ float  g_inv[NS * NSEG];   // 1 / |b-a|^2
__device__ int    g_idcs[NCELL * KK];
__device__ float  g_cw[NCELL * KK];   // width[idcs] per cell slot
__device__ int    g_binCnt[GB*GB];
__device__ int    g_binStart[GB*GB];
__device__ int    g_binCursor[GB*GB];
__device__ int    g_binStroke[NS];
__device__ float2 g_binLoc[NS];

// ---------------- bezier -> segments ----------------
__global__ void bezier_kernel(const float* __restrict__ cs,
                              const float* __restrict__ ce,
                              const float* __restrict__ cc,
                              const float* __restrict__ loc) {
    int n = blockIdx.x * blockDim.x + threadIdx.x;
    if (n >= NS) return;
    float lx = loc[2*n], ly = loc[2*n+1];
    float sx = cs[2*n] + lx, sy = cs[2*n+1] + ly;
    float ex = ce[2*n] + lx, ey = ce[2*n+1] + ly;
    float cx = cc[2*n] + lx, cy = cc[2*n+1] + ly;
    float scx = sx - cx, scy = sy - cy;
    float ecx = ex - cx, ecy = ey - cy;
    float px[SP], py[SP];
    const float step = 1.0f / 9.0f;
    #pragma unroll
    for (int j = 0; j < SP; j++) {
        float t = (float)j * step;
        float omt = 1.0f - t;
        float omt2 = omt * omt, t2 = t * t;
        px[j] = cx + omt2 * scx + t2 * ecx;
        py[j] = cy + omt2 * scy + t2 * ecy;
    }
    #pragma unroll
    for (int q = 0; q < NSEG; q++) {
        float ax = px[q], ay = py[q];
        float bx = px[q+1] - ax, by = py[q+1] - ay;
        g_seg[n*NSEG + q] = make_float4(ax, ay, bx, by);
        g_inv[n*NSEG + q] = 1.0f / (bx*bx + by*by);
    }
}

// ---------------- binning ----------------
__global__ void zero_bins_kernel() {
    int t = threadIdx.x;
    if (t < GB*GB) g_binCnt[t] = 0;
}
__global__ void count_kernel(const float* __restrict__ loc) {
    int n = blockIdx.x * blockDim.x + threadIdx.x;
    if (n >= NS) return;
    float lx = loc[2*n], ly = loc[2*n+1];
    int bx = min(GB-1, (int)(lx * (1.0f/BSZ)));
    int by = min(GB-1, (int)(ly * (1.0f/BSZ)));
    atomicAdd(&g_binCnt[bx*GB + by], 1);
}
__global__ void scan_kernel() {
    __shared__ int sh[GB*GB];
    int t = threadIdx.x;
    sh[t] = g_binCnt[t];
    __syncthreads();
    int acc = 0;
    for (int i = 0; i < t; i++) acc += sh[i];
    g_binStart[t]  = acc;
    g_binCursor[t] = acc;
}
__global__ void scatter_kernel(const float* __restrict__ loc) {
    int n = blockIdx.x * blockDim.x + threadIdx.x;
    if (n >= NS) return;
    float lx = loc[2*n], ly = loc[2*n+1];
    int bx = min(GB-1, (int)(lx * (1.0f/BSZ)));
    int by = min(GB-1, (int)(ly * (1.0f/BSZ)));
    int pos = atomicAdd(&g_binCursor[bx*GB + by], 1);
    g_binStroke[pos] = n;
    g_binLoc[pos] = make_float2(lx, ly);
}

// ---------------- exact top-K per cell via ring expansion ----------------
// key = (dist_bits << 32) | idx  -> u64 ascending == (dist asc, idx asc)
__global__ void topk_cells_kernel(const float* __restrict__ width) {
    int cell = blockIdx.x * blockDim.x + threadIdx.x;
    if (cell >= NCELL) return;
    int cy = cell / HC, cx = cell - cy * HC;
    const float cstep = 512.0f / 101.0f;
    float px = (float)cy * cstep;
    float py = (float)cx * cstep;

    unsigned long long lst[KK];
    #pragma unroll
    for (int j = 0; j < KK; j++) lst[j] = 0xFFFFFFFFFFFFFFFFULL;
    int seen = 0;

    int bx = min(GB-1, (int)(px * (1.0f/BSZ)));
    int by = min(GB-1, (int)(py * (1.0f/BSZ)));

    for (int ring = 0; ring < GB; ring++) {
        if (seen >= KK && ring >= 1) {
            float lb = (float)(ring - 1) * BSZ;
            float kthd = __uint_as_float((unsigned)(lst[KK-1] >> 32));
            if (lb * lb > kthd) break;
        }
        int x0 = max(0, bx - ring), x1 = min(GB-1, bx + ring);
        int y0 = max(0, by - ring), y1 = min(GB-1, by + ring);
        for (int x = x0; x <= x1; x++) {
            for (int y = y0; y <= y1; y++) {
                if (max(abs(x - bx), abs(y - by)) != ring) continue;
                int b  = x * GB + y;
                int st = g_binStart[b];
                int en = st + g_binCnt[b];
                for (int i = st; i < en; i++) {
                    float2 L = g_binLoc[i];
                    float dx = px - L.x, dy = py - L.y;
                    float d = dx*dx + dy*dy;
                    unsigned long long key =
                        ((unsigned long long)__float_as_uint(d) << 32) |
                        (unsigned)g_binStroke[i];
                    if (key < lst[KK-1]) {
                        unsigned long long cur = key;
                        #pragma unroll
                        for (int j = 0; j < KK; j++) {
                            unsigned long long lo = min(cur, lst[j]);
                            unsigned long long hi = max(cur, lst[j]);
                            lst[j] = lo; cur = hi;
                        }
                    }
                    seen++;
                }
            }
        }
    }
    #pragma unroll
    for (int j = 0; j < KK; j++) {
        int idx = (int)(lst[j] & 0xffffffffu);
        g_idcs[cell*KK + j] = idx;
        g_cw[cell*KK + j]   = width[idx];
    }
}

// ---------------- render: one warp per coarse cell ----------------
__global__ void __launch_bounds__(128) render_kernel(const float* __restrict__ color,
                                                     float* __restrict__ out) {
    __shared__ float4 sh_seg[4][NSEG*KK];
    __shared__ float  sh_inv[4][NSEG*KK];
    __shared__ float  sh_w[4][9][KK];
    __shared__ float4 sh_col[4][KK];
    __shared__ int    sh_idx[4][KK];

    int w    = threadIdx.x >> 5;
    int lane = threadIdx.x & 31;
    int cell = blockIdx.x * 4 + w;          // NCELL = 2601*4 exactly
    int cy = cell / HC, cx = cell - cy * HC;

    // stage stroke indices + colors
    if (lane < KK) {
        int s = g_idcs[cell*KK + lane];
        sh_idx[w][lane] = s;
        sh_col[w][lane] = make_float4(__ldg(&color[3*s]), __ldg(&color[3*s+1]),
                                      __ldg(&color[3*s+2]), 0.0f);
    }
    __syncwarp();
    // stage segments
    for (int t = lane; t < NSEG*KK; t += 32) {
        int k = t / NSEG, q = t - k * NSEG;
        int s = sh_idx[w][k];
        sh_seg[w][k*NSEG + q] = __ldg(&g_seg[s*NSEG + q]);
        sh_inv[w][k*NSEG + q] = __ldg(&g_inv[s*NSEG + q]);
    }
    // stage 3x3 neighborhood width lists
    for (int t = lane; t < 9*KK; t += 32) {
        int n = t / KK, k = t - n * KK;
        int ncy = min(HC-1, max(0, cy - 1 + n / 3));
        int ncx = min(HC-1, max(0, cx - 1 + n % 3));
        sh_w[w][n][k] = __ldg(&g_cw[(ncy*HC + ncx)*KK + k]);
    }
    __syncwarp();

    // pixel range of this cell: rows [r0(cy), r0(cy+1))
    int r0 = (cy*256 + 50) / 51, r1 = ((cy+1)*256 + 50) / 51;
    int c0 = (cx*256 + 50) / 51, c1 = ((cx+1)*256 + 50) / 51;
    int nr = r1 - r0, nc = c1 - c0;
    int npix = nr * nc;

    const float fstep = 512.0f / 511.0f;
    const float INF = __int_as_float(0x7f800000);

    for (int p = lane; p < npix; p += 32) {
        int i = r0 + p / nc;
        int j = c0 + p - (p / nc) * nc;
        float Px = (float)i * fstep;
        float Py = (float)j * fstep;

        // width bilinear coords
        float u = ((float)i + 0.5f) * 0.19921875f - 0.5f;
        float v = ((float)j + 0.5f) * 0.19921875f - 0.5f;
        u = fminf(fmaxf(u, 0.0f), 101.0f);
        v = fminf(fmaxf(v, 0.0f), 101.0f);
        int u0 = min((int)u, 100), v0 = min((int)v, 100);
        float fu = u - (float)u0, fv = v - (float)v0;
        float wt00 = (1.0f-fu)*(1.0f-fv), wt01 = (1.0f-fu)*fv;
        float wt10 = fu*(1.0f-fv),        wt11 = fu*fv;
        int ru = u0 - (cy - 1);           // 0..1
        int rv = v0 - (cx - 1);           // 0..1
        int n00 = ru * 3 + rv;

        float Lmax = -INF;
        float Ssum = 0.0f, A0 = 0.0f, A1 = 0.0f, A2 = 0.0f, Wa = 0.0f;
        float Dmin = INF;

        #pragma unroll 1
        for (int k = 0; k < KK; k++) {
            const float4* seg = &sh_seg[w][k*NSEG];
            const float*  inv = &sh_inv[w][k*NSEG];
            float m = INF;
            #pragma unroll
            for (int q = 0; q < NSEG; q++) {
                float4 sg = seg[q];
                float  iv = inv[q];
                float pax = Px - sg.x, pay = Py - sg.y;
                float t = (sg.z * pax + sg.w * pay) * iv;
                t = fminf(fmaxf(t, 0.0f), 1.0f);
                float qx = sg.x + t * sg.z;
                float qy = sg.y + t * sg.w;
                float dx = Px - qx, dy = Py - qy;
                float d = dx*dx + dy*dy;
                m = fminf(m, d);
            }
            Dmin = fminf(Dmin, m);
            float logit = 100000.0f * (1.0f / (1e-8f + m));

            float wk = wt00 * sh_w[w][n00    ][k]
                     + wt01 * sh_w[w][n00 + 1][k]
                     + wt10 * sh_w[w][n00 + 3][k]
                     + wt11 * sh_w[w][n00 + 4][k];

            float4 c = sh_col[w][k];

            float nm = fmaxf(Lmax, logit);
            float so = __expf(Lmax - nm);
            float wt = __expf(logit - nm);
            Ssum = Ssum * so + wt;
            A0 = A0 * so + wt * c.x;
            A1 = A1 * so + wt * c.y;
            A2 = A2 * so + wt * c.z;
            Wa = Wa * so + wt * wk;
            Lmax = nm;
        }

        float invS = 1.0f / Ssum;
        float bs = Wa * invS;
        float x = bs - Dmin;
        float mask = 1.0f / (1.0f + __expf(-x));
        float om = 1.0f - mask;
        int o = (i * HH + j) * 3;
        out[o+0] = A0 * invS * mask + om * 0.5f;
        out[o+1] = A1 * invS * mask + om * 0.5f;
        out[o+2] = A2 * invS * mask + om * 0.5f;
    }
}

// ---------------- launch ----------------
extern "C" void kernel_launch(void* const* d_in, const int* in_sizes, int n_in,
                              void* d_out, int out_size) {
    const float* curve_s  = (const float*)d_in[0];
    const float* curve_e  = (const float*)d_in[1];
    const float* curve_c  = (const float*)d_in[2];
    const float* color    = (const float*)d_in[3];
    const float* location = (const float*)d_in[4];
    const float* width    = (const float*)d_in[5];
    float* out = (float*)d_out;

    zero_bins_kernel<<<1, 256>>>();
    bezier_kernel<<<(NS + 127) / 128, 128>>>(curve_s, curve_e, curve_c, location);
    count_kernel<<<(NS + 255) / 256, 256>>>(location);
    scan_kernel<<<1, 256>>>();
    scatter_kernel<<<(NS + 255) / 256, 256>>>(location);
    topk_cells_kernel<<<(NCELL + 127) / 128, 128>>>(width);
    render_kernel<<<NCELL / 4, 128>>>(color, out);
}

// round 7
// speedup vs baseline: 11.5944x; 1.0931x over previous
#include <cuda_runtime.h>
#include <cuda_bf16.h>

#define NS    5000
#define SP    10
#define NSEG  9
#define HH    512
#define HC    102
#define KK    20
#define GB    16
#define BSZ   32.0f
#define NCELL (HC*HC)

// ---- device scratch ----
__device__ float4 g_seg[NS * NSEG];
__device__ float  g_inv[NS * NSEG];
__device__ int    g_idcs[NCELL * KK];
__device__ float  g_cw[NCELL * KK];
__device__ int    g_binCnt[GB*GB];
__device__ int    g_binStart[GB*GB];
__device__ int    g_binStroke[NS];
__device__ float2 g_binLoc[NS];

// ---------------- bezier -> segments ----------------
__global__ void bezier_kernel(const float* __restrict__ cs,
                              const float* __restrict__ ce,
                              const float* __restrict__ cc,
                              const float* __restrict__ loc) {
    int n = blockIdx.x * blockDim.x + threadIdx.x;
    if (n >= NS) return;
    float lx = loc[2*n], ly = loc[2*n+1];
    float sx = cs[2*n] + lx, sy = cs[2*n+1] + ly;
    float ex = ce[2*n] + lx, ey = ce[2*n+1] + ly;
    float cx = cc[2*n] + lx, cy = cc[2*n+1] + ly;
    float scx = sx - cx, scy = sy - cy;
    float ecx = ex - cx, ecy = ey - cy;
    float px[SP], py[SP];
    const float step = 1.0f / 9.0f;
    #pragma unroll
    for (int j = 0; j < SP; j++) {
        float t = (float)j * step;
        float omt = 1.0f - t;
        float omt2 = omt * omt, t2 = t * t;
        px[j] = cx + omt2 * scx + t2 * ecx;
        py[j] = cy + omt2 * scy + t2 * ecy;
    }
    #pragma unroll
    for (int q = 0; q < NSEG; q++) {
        float ax = px[q], ay = py[q];
        float bx = px[q+1] - ax, by = py[q+1] - ay;
        g_seg[n*NSEG + q] = make_float4(ax, ay, bx, by);
        g_inv[n*NSEG + q] = 1.0f / (bx*bx + by*by);
    }
}

// ---------------- fused binning: zero+count+scan+scatter ----------------
__global__ void bin_kernel(const float* __restrict__ loc) {
    __shared__ int cnt[GB*GB];
    __shared__ int scanv[GB*GB];
    __shared__ int cur[GB*GB];
    int t = threadIdx.x;                      // 1024 threads, 1 block
    if (t < GB*GB) cnt[t] = 0;
    __syncthreads();
    for (int n = t; n < NS; n += 1024) {
        float lx = loc[2*n], ly = loc[2*n+1];
        int bx = min(GB-1, (int)(lx * (1.0f/BSZ)));
        int by = min(GB-1, (int)(ly * (1.0f/BSZ)));
        atomicAdd(&cnt[bx*GB + by], 1);
    }
    __syncthreads();
    if (t < GB*GB) scanv[t] = cnt[t];
    __syncthreads();
    #pragma unroll
    for (int off = 1; off < GB*GB; off <<= 1) {
        int v = 0;
        if (t < GB*GB && t >= off) v = scanv[t - off];
        __syncthreads();
        if (t < GB*GB) scanv[t] += v;
        __syncthreads();
    }
    if (t < GB*GB) {
        int ex = scanv[t] - cnt[t];
        g_binStart[t] = ex;
        g_binCnt[t]   = cnt[t];
        cur[t] = ex;
    }
    __syncthreads();
    for (int n = t; n < NS; n += 1024) {
        float lx = loc[2*n], ly = loc[2*n+1];
        int bx = min(GB-1, (int)(lx * (1.0f/BSZ)));
        int by = min(GB-1, (int)(ly * (1.0f/BSZ)));
        int pos = atomicAdd(&cur[bx*GB + by], 1);
        g_binStroke[pos] = n;
        g_binLoc[pos] = make_float2(lx, ly);
    }
}

// ---------------- exact top-K per cell: one WARP per cell ----------------
// key = (dist_bits << 32) | idx -> u64 asc == (dist asc, idx asc) == top_k tie rule
__global__ void __launch_bounds__(128) topk_kernel(const float* __restrict__ width) {
    __shared__ unsigned long long lists[4][32][KK];
    int lane = threadIdx.x & 31;
    int wi   = threadIdx.x >> 5;
    int cell = blockIdx.x * 4 + wi;           // NCELL = 2601*4
    int cy = cell / HC, cx = cell - cy * HC;
    const float cstep = 512.0f / 101.0f;
    float px = (float)cy * cstep;
    float py = (float)cx * cstep;

    unsigned long long lst[KK];
    #pragma unroll
    for (int j = 0; j < KK; j++) lst[j] = 0xFFFFFFFFFFFFFFFFULL;

    int bx = min(GB-1, (int)(px * (1.0f/BSZ)));
    int by = min(GB-1, (int)(py * (1.0f/BSZ)));

    for (int ring = 0; ring < GB; ring++) {
        if (ring >= 1) {
            // unscanned strokes have d >= (ring-1)*BSZ. If >=20 found strictly
            // closer, top-20 is settled.
            float b = (float)(ring - 1) * BSZ;
            float b2 = b * b;
            int c = 0;
            #pragma unroll
            for (int j = 0; j < KK; j++)
                c += (__uint_as_float((unsigned)(lst[j] >> 32)) < b2) ? 1 : 0;
            int tot = __reduce_add_sync(0xffffffffu, c);
            if (tot >= KK) break;
        }
        int x0 = max(0, bx - ring), x1 = min(GB-1, bx + ring);
        int y0 = max(0, by - ring), y1 = min(GB-1, by + ring);
        for (int x = x0; x <= x1; x++) {
            for (int y = y0; y <= y1; y++) {
                if (max(abs(x - bx), abs(y - by)) != ring) continue;
                int b  = x * GB + y;
                int st = g_binStart[b];
                int en = st + g_binCnt[b];
                for (int i = st + lane; i < en; i += 32) {
                    float2 L = g_binLoc[i];
                    float dx = px - L.x, dy = py - L.y;
                    float d = dx*dx + dy*dy;
                    unsigned long long key =
                        ((unsigned long long)__float_as_uint(d) << 32) |
                        (unsigned)g_binStroke[i];
                    if (key < lst[KK-1]) {
                        unsigned long long c2 = key;
                        #pragma unroll
                        for (int j = 0; j < KK; j++) {
                            unsigned long long lo = min(c2, lst[j]);
                            unsigned long long hi = max(c2, lst[j]);
                            lst[j] = lo; c2 = hi;
                        }
                    }
                }
            }
        }
    }

    unsigned long long* my = lists[wi][lane];
    #pragma unroll
    for (int j = 0; j < KK; j++) my[j] = lst[j];
    __syncwarp();

    int h = 0;
    for (int r = 0; r < KK; r++) {
        unsigned long long mykey = my[h];
        unsigned long long mn = mykey;
        #pragma unroll
        for (int off = 16; off; off >>= 1) {
            unsigned long long o = __shfl_xor_sync(0xffffffffu, mn, off);
            if (o < mn) mn = o;
        }
        unsigned msk = __ballot_sync(0xffffffffu, mykey == mn);
        int leader = __ffs(msk) - 1;
        if (lane == leader) h++;
        if (lane == 0) {
            int idx = (int)(mn & 0xffffffffu);
            g_idcs[cell*KK + r] = idx;
            g_cw[cell*KK + r]   = __ldg(&width[idx]);
        }
    }
}

// ---------------- render: one warp per coarse cell ----------------
__global__ void __launch_bounds__(128) render_kernel(const float* __restrict__ color,
                                                     float* __restrict__ out) {
    __shared__ float4 sh_seg[4][NSEG*KK];
    __shared__ float  sh_inv[4][NSEG*KK];
    __shared__ float  sh_w[4][9][KK];
    __shared__ float4 sh_col[4][KK];
    __shared__ int    sh_idx[4][KK];

    int w    = threadIdx.x >> 5;
    int lane = threadIdx.x & 31;
    int cell = blockIdx.x * 4 + w;
    int cy = cell / HC, cx = cell - cy * HC;

    if (lane < KK) {
        int s = g_idcs[cell*KK + lane];
        sh_idx[w][lane] = s;
        sh_col[w][lane] = make_float4(__ldg(&color[3*s]), __ldg(&color[3*s+1]),
                                      __ldg(&color[3*s+2]), 0.0f);
    }
    __syncwarp();
    for (int t = lane; t < NSEG*KK; t += 32) {
        int k = t / NSEG, q = t - k * NSEG;
        int s = sh_idx[w][k];
        sh_seg[w][k*NSEG + q] = __ldg(&g_seg[s*NSEG + q]);
        sh_inv[w][k*NSEG + q] = __ldg(&g_inv[s*NSEG + q]);
    }
    for (int t = lane; t < 9*KK; t += 32) {
        int n = t / KK, k = t - n * KK;
        int ncy = min(HC-1, max(0, cy - 1 + n / 3));
        int ncx = min(HC-1, max(0, cx - 1 + n % 3));
        sh_w[w][n][k] = __ldg(&g_cw[(ncy*HC + ncx)*KK + k]);
    }
    __syncwarp();

    int r0 = (cy*256 + 50) / 51, r1 = ((cy+1)*256 + 50) / 51;
    int c0 = (cx*256 + 50) / 51, c1 = ((cx+1)*256 + 50) / 51;
    int nr = r1 - r0, nc = c1 - c0;
    int npix = nr * nc;

    const float fstep = 512.0f / 511.0f;
    const float INF = __int_as_float(0x7f800000);

    for (int p = lane; p < npix; p += 32) {
        int i = r0 + p / nc;
        int j = c0 + p - (p / nc) * nc;
        float Px = (float)i * fstep;
        float Py = (float)j * fstep;

        float u = ((float)i + 0.5f) * 0.19921875f - 0.5f;
        float v = ((float)j + 0.5f) * 0.19921875f - 0.5f;
        u = fminf(fmaxf(u, 0.0f), 101.0f);
        v = fminf(fmaxf(v, 0.0f), 101.0f);
        int u0 = min((int)u, 100), v0 = min((int)v, 100);
        float fu = u - (float)u0, fv = v - (float)v0;
        float wt00 = (1.0f-fu)*(1.0f-fv), wt01 = (1.0f-fu)*fv;
        float wt10 = fu*(1.0f-fv),        wt11 = fu*fv;
        int n00 = (u0 - (cy - 1)) * 3 + (v0 - (cx - 1));

        // pass 1: distances + logits + max
        float logitv[KK];
        float Lmax = -INF;
        float Dmin = INF;
        #pragma unroll 1
        for (int k = 0; k < KK; k++) {
            const float4* seg = &sh_seg[w][k*NSEG];
            const float*  inv = &sh_inv[w][k*NSEG];
            float m = INF;
            #pragma unroll
            for (int q = 0; q < NSEG; q++) {
                float4 sg = seg[q];
                float  iv = inv[q];
                float pax = Px - sg.x, pay = Py - sg.y;
                float t = (sg.z * pax + sg.w * pay) * iv;
                t = fminf(fmaxf(t, 0.0f), 1.0f);
                float qx = sg.x + t * sg.z;
                float qy = sg.y + t * sg.w;
                float dx = Px - qx, dy = Py - qy;
                float d = dx*dx + dy*dy;
                m = fminf(m, d);
            }
            Dmin = fminf(Dmin, m);
            float logit = 100000.0f * (1.0f / (1e-8f + m));
            logitv[k] = logit;
            Lmax = fmaxf(Lmax, logit);
        }

        // pass 2: softmax accumulation (== exp(x - max) / sum)
        float Ssum = 0.0f, A0 = 0.0f, A1 = 0.0f, A2 = 0.0f, Wa = 0.0f;
        #pragma unroll
        for (int k = 0; k < KK; k++) {
            float wt = __expf(logitv[k] - Lmax);
            float wk = wt00 * sh_w[w][n00    ][k]
                     + wt01 * sh_w[w][n00 + 1][k]
                     + wt10 * sh_w[w][n00 + 3][k]
                     + wt11 * sh_w[w][n00 + 4][k];
            float4 c = sh_col[w][k];
            Ssum += wt;
            A0 = fmaf(wt, c.x, A0);
            A1 = fmaf(wt, c.y, A1);
            A2 = fmaf(wt, c.z, A2);
            Wa = fmaf(wt, wk, Wa);
        }

        float invS = 1.0f / Ssum;
        float bs = Wa * invS;
        float x = bs - Dmin;
        float mask = 1.0f / (1.0f + __expf(-x));
        float om = 1.0f - mask;
        int o = (i * HH + j) * 3;
        out[o+0] = A0 * invS * mask + om * 0.5f;
        out[o+1] = A1 * invS * mask + om * 0.5f;
        out[o+2] = A2 * invS * mask + om * 0.5f;
    }
}

// ---------------- launch ----------------
extern "C" void kernel_launch(void* const* d_in, const int* in_sizes, int n_in,
                              void* d_out, int out_size) {
    const float* curve_s  = (const float*)d_in[0];
    const float* curve_e  = (const float*)d_in[1];
    const float* curve_c  = (const float*)d_in[2];
    const float* color    = (const float*)d_in[3];
    const float* location = (const float*)d_in[4];
    const float* width    = (const float*)d_in[5];
    float* out = (float*)d_out;

    bezier_kernel<<<(NS + 127) / 128, 128>>>(curve_s, curve_e, curve_c, location);
    bin_kernel<<<1, 1024>>>(location);
    topk_kernel<<<NCELL / 4, 128>>>(width);
    render_kernel<<<NCELL / 4, 128>>>(color, out);
}